// round 4
// baseline (speedup 1.0000x reference)
#include <cuda_runtime.h>
#include <cstdint>

#define N_NODES 50000
#define N_EDGES 800000
#define D_IN 128
#define H_DIM 128
#define D_OUT 64

#define SCAN_BLK 256
#define NBLK ((N_NODES + SCAN_BLK - 1) / SCAN_BLK)   // 196

typedef unsigned long long ull;

// ---------------- device scratch (static, no allocation) ----------------
__device__ float g_vs1[N_NODES * 256];   // layer1 GEMM out: [v(128) | s(128)] per node
__device__ float g_vs2[N_NODES * 128];   // layer2 GEMM out: [u(64) | r(64)] per node
__device__ int   g_deg[N_NODES];
__device__ int   g_off[N_NODES + 1];
__device__ int   g_cursor[N_NODES];
__device__ int   g_csr[N_EDGES];
__device__ int   g_bsum[NBLK];
__device__ int   g_is64;

// ---------------- zero degrees + int64/int32 detection (fused) ----------------
__global__ void k_zero_detect(const int* __restrict__ ei32) {
    int i = blockIdx.x * blockDim.x + threadIdx.x;
    if (i < N_NODES) g_deg[i] = 0;
    if (i == 0) {
        int orv = 0;
#pragma unroll
        for (int k = 0; k < 64; k++) orv |= ei32[2 * k + 1];
        g_is64 = (orv == 0) ? 1 : 0;
    }
}

__global__ void k_hist(const void* __restrict__ ei) {
    int e = blockIdx.x * blockDim.x + threadIdx.x;
    if (e >= N_EDGES) return;
    int dst = g_is64 ? (int)((const long long*)ei)[N_EDGES + e]
                     : ((const int*)ei)[N_EDGES + e];
    atomicAdd(&g_deg[dst], 1);
}

// ---------------- parallel 3-phase scan ----------------
__global__ void k_scan1() {
    __shared__ int sh[SCAN_BLK];
    int i = blockIdx.x * SCAN_BLK + threadIdx.x;
    int v = (i < N_NODES) ? g_deg[i] : 0;
    sh[threadIdx.x] = v;
    __syncthreads();
    for (int off = SCAN_BLK / 2; off > 0; off >>= 1) {
        if (threadIdx.x < off) sh[threadIdx.x] += sh[threadIdx.x + off];
        __syncthreads();
    }
    if (threadIdx.x == 0) g_bsum[blockIdx.x] = sh[0];
}

__global__ void k_scan2() {
    __shared__ int sh[SCAN_BLK];
    int t = threadIdx.x;
    int v = (t < NBLK) ? g_bsum[t] : 0;
    sh[t] = v;
    __syncthreads();
    for (int off = 1; off < SCAN_BLK; off <<= 1) {
        int add = (t >= off) ? sh[t - off] : 0;
        __syncthreads();
        sh[t] += add;
        __syncthreads();
    }
    if (t < NBLK) g_bsum[t] = sh[t] - v;          // exclusive
    if (t == 0) g_off[N_NODES] = N_EDGES;
}

__global__ void k_scan3() {
    __shared__ int sh[SCAN_BLK];
    int t = threadIdx.x;
    int i = blockIdx.x * SCAN_BLK + t;
    int v = (i < N_NODES) ? g_deg[i] : 0;
    sh[t] = v;
    __syncthreads();
    for (int off = 1; off < SCAN_BLK; off <<= 1) {
        int add = (t >= off) ? sh[t - off] : 0;
        __syncthreads();
        sh[t] += add;
        __syncthreads();
    }
    if (i < N_NODES) {
        int o = g_bsum[blockIdx.x] + sh[t] - v;    // exclusive global offset
        g_off[i] = o;
        g_cursor[i] = o;
    }
}

__global__ void k_scatter(const void* __restrict__ ei) {
    int e = blockIdx.x * blockDim.x + threadIdx.x;
    if (e >= N_EDGES) return;
    int src, dst;
    if (g_is64) {
        src = (int)((const long long*)ei)[e];
        dst = (int)((const long long*)ei)[N_EDGES + e];
    } else {
        src = ((const int*)ei)[e];
        dst = ((const int*)ei)[N_EDGES + e];
    }
    int pos = atomicAdd(&g_cursor[dst], 1);
    g_csr[pos] = src;
}

// ---------------- f32x2 helpers ----------------
__device__ __forceinline__ void fma2(ull& d, ull a, ull b) {
    asm("fma.rn.f32x2 %0, %1, %2, %0;" : "+l"(d) : "l"(a), "l"(b));
}
__device__ __forceinline__ ull dup2(float x) {
    ull r;
    asm("mov.b64 %0, {%1, %1};" : "=l"(r) : "f"(x));
    return r;
}
__device__ __forceinline__ void unpack2(ull v, float& lo, float& hi) {
    asm("mov.b64 {%0, %1}, %2;" : "=f"(lo), "=f"(hi) : "l"(v));
}

// ---------------- layer-1 GEMM: out[n] = [x.Wrel1 | x.Wroot1 + b1], f32x2 FMA ----------------
// Register-prefetch double buffering: next tile's LDGs issue under current compute.
template <int HOUT>
__global__ void __launch_bounds__(256, 1)
k_gemm(const float* __restrict__ X,
       const float* __restrict__ Wa, const float* __restrict__ Wb,
       const float* __restrict__ bias, float* __restrict__ out) {
    constexpr int H2 = HOUT / 2;
    constexpr int J2 = HOUT / 32;
    constexpr int S  = HOUT + 8;
    extern __shared__ float smf[];
    float*  Wt  = smf;                       // [128][S]
    float4* As4 = (float4*)(smf + 128 * S);  // [64][33]
    const int tid = threadIdx.x;
    const float4* X4 = (const float4*)X;

    for (int idx = tid; idx < H2 * 128; idx += 256) {
        int h = idx >> 7, k = idx & 127;
        Wt[k * S + h]      = Wa[idx];
        Wt[k * S + H2 + h] = Wb[idx];
    }

    const int tx = tid & 15, ty = tid >> 4;
    const int NT = (N_NODES + 63) >> 6;

    // prefetch first tile into registers
    float4 pre[8];
    {
        int t0 = blockIdx.x;
        if (t0 < NT) {
            int n0 = t0 << 6;
#pragma unroll
            for (int u = 0; u < 8; u++) {
                int idx = tid + u * 256;
                int r = idx >> 5, kq = idx & 31;
                int n = n0 + r;
                pre[u] = (n < N_NODES) ? X4[n * 32 + kq]
                                       : make_float4(0.f, 0.f, 0.f, 0.f);
            }
        }
    }
    __syncthreads();   // Wt staged

    for (int tile = blockIdx.x; tile < NT; tile += gridDim.x) {
        const int n0 = tile << 6;
        // commit prefetched tile to smem
#pragma unroll
        for (int u = 0; u < 8; u++) {
            int idx = tid + u * 256;
            As4[(idx >> 5) * 33 + (idx & 31)] = pre[u];
        }
        __syncthreads();

        // issue next tile's loads now; they complete under the FMA stream
        int nt = tile + gridDim.x;
        if (nt < NT) {
            int m0 = nt << 6;
#pragma unroll
            for (int u = 0; u < 8; u++) {
                int idx = tid + u * 256;
                int r = idx >> 5, kq = idx & 31;
                int n = m0 + r;
                pre[u] = (n < N_NODES) ? X4[n * 32 + kq]
                                       : make_float4(0.f, 0.f, 0.f, 0.f);
            }
        }

        ull acc[4][J2];
#pragma unroll
        for (int i = 0; i < 4; i++)
#pragma unroll
            for (int j = 0; j < J2; j++) acc[i][j] = 0ull;

        const float4* Ar = As4 + (ty * 4) * 33;
#pragma unroll 2
        for (int kq = 0; kq < 32; kq++) {
            float4 a0 = Ar[kq];
            float4 a1 = Ar[33 + kq];
            float4 a2 = Ar[66 + kq];
            float4 a3 = Ar[99 + kq];
            ull aa[4][4];
            aa[0][0] = dup2(a0.x); aa[0][1] = dup2(a0.y); aa[0][2] = dup2(a0.z); aa[0][3] = dup2(a0.w);
            aa[1][0] = dup2(a1.x); aa[1][1] = dup2(a1.y); aa[1][2] = dup2(a1.z); aa[1][3] = dup2(a1.w);
            aa[2][0] = dup2(a2.x); aa[2][1] = dup2(a2.y); aa[2][2] = dup2(a2.z); aa[2][3] = dup2(a2.w);
            aa[3][0] = dup2(a3.x); aa[3][1] = dup2(a3.y); aa[3][2] = dup2(a3.z); aa[3][3] = dup2(a3.w);
#pragma unroll
            for (int c = 0; c < 4; c++) {
                const float* wrow = &Wt[(kq * 4 + c) * S];
#pragma unroll
                for (int j = 0; j < J2; j++) {
                    ull w2 = *(const ull*)&wrow[tx * 2 + j * 32];
                    fma2(acc[0][j], aa[0][c], w2);
                    fma2(acc[1][j], aa[1][c], w2);
                    fma2(acc[2][j], aa[2][c], w2);
                    fma2(acc[3][j], aa[3][c], w2);
                }
            }
        }

#pragma unroll
        for (int i = 0; i < 4; i++) {
            int n = n0 + ty * 4 + i;
            if (n < N_NODES) {
#pragma unroll
                for (int j = 0; j < J2; j++) {
                    int h0 = tx * 2 + j * 32;
                    float lo, hi;
                    unpack2(acc[i][j], lo, hi);
                    if (j >= J2 / 2) {                  // root half gets bias
                        lo += __ldg(&bias[h0 - H2]);
                        hi += __ldg(&bias[h0 - H2 + 1]);
                    }
                    *(float2*)&out[n * HOUT + h0] = make_float2(lo, hi);
                }
            }
        }
        __syncthreads();
    }
}

// ---------------- fused layer-2: gather-aggregate(relu) + GEMM ----------------
// A-tile row r (node n) is built in-place: relu( s_n + sum_{src in N(n)} v_src ).
// Then out[n] = [t.Wrel2 | t.Wroot2 + b2], same f32x2 compute as k_gemm<128>.
__global__ void __launch_bounds__(256, 1)
k_fused2(const float4* __restrict__ vs1,
         const float* __restrict__ Wa, const float* __restrict__ Wb,
         const float* __restrict__ bias, float* __restrict__ out) {
    constexpr int HOUT = 128, H2 = 64, J2 = 4, S = HOUT + 8;
    extern __shared__ float smf[];
    float*  Wt  = smf;                       // [128][S]
    float4* As4 = (float4*)(smf + 128 * S);  // [64][33]
    const int tid = threadIdx.x;
    const int lane = tid & 31, wid = tid >> 5;

    for (int idx = tid; idx < H2 * 128; idx += 256) {
        int h = idx >> 7, k = idx & 127;
        Wt[k * S + h]      = Wa[idx];
        Wt[k * S + H2 + h] = Wb[idx];
    }
    __syncthreads();

    const int tx = tid & 15, ty = tid >> 4;
    const int NT = (N_NODES + 63) >> 6;

    for (int tile = blockIdx.x; tile < NT; tile += gridDim.x) {
        const int n0 = tile << 6;

        // gather phase: 8 warps x 8 nodes, float4 lanes over the 128-dim row
#pragma unroll
        for (int i = 0; i < 8; i++) {
            int r = wid * 8 + i;
            int n = n0 + r;
            float4 acc = make_float4(0.f, 0.f, 0.f, 0.f);
            if (n < N_NODES) {
                acc = vs1[n * 64 + 32 + lane];            // s row
                int beg = g_off[n], end = g_off[n + 1];
                int j = beg;
                for (; j + 4 <= end; j += 4) {
                    int s0 = g_csr[j], s1 = g_csr[j + 1];
                    int s2 = g_csr[j + 2], s3 = g_csr[j + 3];
                    float4 a = vs1[s0 * 64 + lane];
                    float4 b = vs1[s1 * 64 + lane];
                    float4 c = vs1[s2 * 64 + lane];
                    float4 d = vs1[s3 * 64 + lane];
                    acc.x += (a.x + b.x) + (c.x + d.x);
                    acc.y += (a.y + b.y) + (c.y + d.y);
                    acc.z += (a.z + b.z) + (c.z + d.z);
                    acc.w += (a.w + b.w) + (c.w + d.w);
                }
                for (; j < end; j++) {
                    float4 a = vs1[g_csr[j] * 64 + lane];
                    acc.x += a.x; acc.y += a.y; acc.z += a.z; acc.w += a.w;
                }
                acc.x = fmaxf(acc.x, 0.f); acc.y = fmaxf(acc.y, 0.f);
                acc.z = fmaxf(acc.z, 0.f); acc.w = fmaxf(acc.w, 0.f);
            }
            As4[r * 33 + lane] = acc;
        }
        __syncthreads();

        ull acc[4][J2];
#pragma unroll
        for (int i = 0; i < 4; i++)
#pragma unroll
            for (int j = 0; j < J2; j++) acc[i][j] = 0ull;

        const float4* Ar = As4 + (ty * 4) * 33;
#pragma unroll 2
        for (int kq = 0; kq < 32; kq++) {
            float4 a0 = Ar[kq];
            float4 a1 = Ar[33 + kq];
            float4 a2 = Ar[66 + kq];
            float4 a3 = Ar[99 + kq];
            ull aa[4][4];
            aa[0][0] = dup2(a0.x); aa[0][1] = dup2(a0.y); aa[0][2] = dup2(a0.z); aa[0][3] = dup2(a0.w);
            aa[1][0] = dup2(a1.x); aa[1][1] = dup2(a1.y); aa[1][2] = dup2(a1.z); aa[1][3] = dup2(a1.w);
            aa[2][0] = dup2(a2.x); aa[2][1] = dup2(a2.y); aa[2][2] = dup2(a2.z); aa[2][3] = dup2(a2.w);
            aa[3][0] = dup2(a3.x); aa[3][1] = dup2(a3.y); aa[3][2] = dup2(a3.z); aa[3][3] = dup2(a3.w);
#pragma unroll
            for (int c = 0; c < 4; c++) {
                const float* wrow = &Wt[(kq * 4 + c) * S];
#pragma unroll
                for (int j = 0; j < J2; j++) {
                    ull w2 = *(const ull*)&wrow[tx * 2 + j * 32];
                    fma2(acc[0][j], aa[0][c], w2);
                    fma2(acc[1][j], aa[1][c], w2);
                    fma2(acc[2][j], aa[2][c], w2);
                    fma2(acc[3][j], aa[3][c], w2);
                }
            }
        }

#pragma unroll
        for (int i = 0; i < 4; i++) {
            int n = n0 + ty * 4 + i;
            if (n < N_NODES) {
#pragma unroll
                for (int j = 0; j < J2; j++) {
                    int h0 = tx * 2 + j * 32;
                    float lo, hi;
                    unpack2(acc[i][j], lo, hi);
                    if (j >= J2 / 2) {
                        lo += __ldg(&bias[h0 - H2]);
                        hi += __ldg(&bias[h0 - H2 + 1]);
                    }
                    *(float2*)&out[n * HOUT + h0] = make_float2(lo, hi);
                }
            }
        }
        __syncthreads();
    }
}

// ---------------- layer-2 aggregation: out[n] = sum u[src] + r[n]  (64-dim) ----------------
__global__ void k_agg2(const float2* __restrict__ ur, float2* __restrict__ out) {
    int gw = (blockIdx.x * blockDim.x + threadIdx.x) >> 5;
    int lane = threadIdx.x & 31;
    if (gw >= N_NODES) return;
    int beg = g_off[gw], end = g_off[gw + 1];
    float2 acc = ur[gw * 64 + 32 + lane];          // r row
    int j = beg;
    for (; j + 4 <= end; j += 4) {
        int s0 = g_csr[j], s1 = g_csr[j + 1], s2 = g_csr[j + 2], s3 = g_csr[j + 3];
        float2 a = ur[s0 * 64 + lane];
        float2 b = ur[s1 * 64 + lane];
        float2 c = ur[s2 * 64 + lane];
        float2 d = ur[s3 * 64 + lane];
        acc.x += (a.x + b.x) + (c.x + d.x);
        acc.y += (a.y + b.y) + (c.y + d.y);
    }
    for (; j < end; j++) {
        float2 a = ur[g_csr[j] * 64 + lane];
        acc.x += a.x; acc.y += a.y;
    }
    out[gw * 32 + lane] = acc;
}

// ---------------- launch: CSR chain forked onto a side stream ----------------
extern "C" void kernel_launch(void* const* d_in, const int* in_sizes, int n_in,
                              void* d_out, int out_size) {
    const float* x      = (const float*)d_in[0];
    const void*  ei     = d_in[1];
    const float* Wrel1  = (const float*)d_in[2];
    const float* Wroot1 = (const float*)d_in[3];
    const float* b1     = (const float*)d_in[4];
    const float* Wrel2  = (const float*)d_in[5];
    const float* Wroot2 = (const float*)d_in[6];
    const float* b2     = (const float*)d_in[7];

    void *p_vs1 = nullptr, *p_vs2 = nullptr;
    cudaGetSymbolAddress(&p_vs1, g_vs1);
    cudaGetSymbolAddress(&p_vs2, g_vs2);

    const int SM1 = (128 * (256 + 8)) * 4 + 64 * 33 * 16;   // 168,960 B
    const int SM2 = (128 * (128 + 8)) * 4 + 64 * 33 * 16;   // 103,424 B
    cudaFuncSetAttribute(k_gemm<256>, cudaFuncAttributeMaxDynamicSharedMemorySize, SM1);
    cudaFuncSetAttribute(k_fused2, cudaFuncAttributeMaxDynamicSharedMemorySize, SM2);

    static cudaStream_t s1 = nullptr;
    static cudaEvent_t evRoot = nullptr, evCsr = nullptr;
    if (s1 == nullptr) {
        cudaStreamCreateWithFlags(&s1, cudaStreamNonBlocking);
        cudaEventCreateWithFlags(&evRoot, cudaEventDisableTiming);
        cudaEventCreateWithFlags(&evCsr, cudaEventDisableTiming);
    }

    // fork: CSR build on s1, concurrent with layer-1 GEMM on stream 0
    cudaEventRecord(evRoot, 0);
    cudaStreamWaitEvent(s1, evRoot, 0);
    k_zero_detect<<<(N_NODES + 255) / 256, 256, 0, s1>>>((const int*)ei);
    k_hist<<<(N_EDGES + 255) / 256, 256, 0, s1>>>(ei);
    k_scan1<<<NBLK, SCAN_BLK, 0, s1>>>();
    k_scan2<<<1, SCAN_BLK, 0, s1>>>();
    k_scan3<<<NBLK, SCAN_BLK, 0, s1>>>();
    k_scatter<<<(N_EDGES + 255) / 256, 256, 0, s1>>>(ei);
    cudaEventRecord(evCsr, s1);

    // layer-1 GEMM x -> [v|s] (independent of CSR)
    k_gemm<256><<<148, 256, SM1>>>(x, Wrel1, Wroot1, b1, (float*)p_vs1);

    // join: fused layer 2 needs both GEMM1 output and the CSR
    cudaStreamWaitEvent(0, evCsr, 0);
    k_fused2<<<148, 256, SM2>>>((const float4*)p_vs1, Wrel2, Wroot2, b2, (float*)p_vs2);

    // final aggregation
    k_agg2<<<(N_NODES * 32 + 255) / 256, 256>>>((const float2*)p_vs2, (float2*)d_out);
}

// round 5
// speedup vs baseline: 1.1499x; 1.1499x over previous
#include <cuda_runtime.h>
#include <cstdint>

#define N_NODES 50000
#define N_EDGES 800000
#define D_IN 128
#define H_DIM 128
#define D_OUT 64

#define SCAN_BLK 256
#define NBLK ((N_NODES + SCAN_BLK - 1) / SCAN_BLK)   // 196

#define NTILES ((N_NODES + 63) / 64)                 // 782
#define NCHUNK 4

typedef unsigned long long ull;

// ---------------- device scratch (static, no allocation) ----------------
__device__ float g_vs1[N_NODES * 256];   // layer1 GEMM out: [v(128) | s(128)] per node
__device__ float g_t1 [N_NODES * 128];   // layer1 activations
__device__ float g_vs2[N_NODES * 128];   // layer2 GEMM out: [u(64) | r(64)] per node
__device__ int   g_deg[N_NODES];
__device__ int   g_off[N_NODES + 1];
__device__ int   g_cursor[N_NODES];
__device__ int   g_csr[N_EDGES];
__device__ int   g_bsum[NBLK];
__device__ int   g_is64;

// ---------------- zero degrees + int64/int32 detection (fused) ----------------
__global__ void k_zero_detect(const int* __restrict__ ei32) {
    int i = blockIdx.x * blockDim.x + threadIdx.x;
    if (i < N_NODES) g_deg[i] = 0;
    if (i == 0) {
        int orv = 0;
#pragma unroll
        for (int k = 0; k < 64; k++) orv |= ei32[2 * k + 1];
        g_is64 = (orv == 0) ? 1 : 0;
    }
}

__global__ void k_hist(const void* __restrict__ ei) {
    int e = blockIdx.x * blockDim.x + threadIdx.x;
    if (e >= N_EDGES) return;
    int dst = g_is64 ? (int)((const long long*)ei)[N_EDGES + e]
                     : ((const int*)ei)[N_EDGES + e];
    atomicAdd(&g_deg[dst], 1);
}

// ---------------- parallel 3-phase scan ----------------
__global__ void k_scan1() {
    __shared__ int sh[SCAN_BLK];
    int i = blockIdx.x * SCAN_BLK + threadIdx.x;
    int v = (i < N_NODES) ? g_deg[i] : 0;
    sh[threadIdx.x] = v;
    __syncthreads();
    for (int off = SCAN_BLK / 2; off > 0; off >>= 1) {
        if (threadIdx.x < off) sh[threadIdx.x] += sh[threadIdx.x + off];
        __syncthreads();
    }
    if (threadIdx.x == 0) g_bsum[blockIdx.x] = sh[0];
}

__global__ void k_scan2() {
    __shared__ int sh[SCAN_BLK];
    int t = threadIdx.x;
    int v = (t < NBLK) ? g_bsum[t] : 0;
    sh[t] = v;
    __syncthreads();
    for (int off = 1; off < SCAN_BLK; off <<= 1) {
        int add = (t >= off) ? sh[t - off] : 0;
        __syncthreads();
        sh[t] += add;
        __syncthreads();
    }
    if (t < NBLK) g_bsum[t] = sh[t] - v;          // exclusive
    if (t == 0) g_off[N_NODES] = N_EDGES;
}

__global__ void k_scan3() {
    __shared__ int sh[SCAN_BLK];
    int t = threadIdx.x;
    int i = blockIdx.x * SCAN_BLK + t;
    int v = (i < N_NODES) ? g_deg[i] : 0;
    sh[t] = v;
    __syncthreads();
    for (int off = 1; off < SCAN_BLK; off <<= 1) {
        int add = (t >= off) ? sh[t - off] : 0;
        __syncthreads();
        sh[t] += add;
        __syncthreads();
    }
    if (i < N_NODES) {
        int o = g_bsum[blockIdx.x] + sh[t] - v;    // exclusive global offset
        g_off[i] = o;
        g_cursor[i] = o;
    }
}

__global__ void k_scatter(const void* __restrict__ ei) {
    int e = blockIdx.x * blockDim.x + threadIdx.x;
    if (e >= N_EDGES) return;
    int src, dst;
    if (g_is64) {
        src = (int)((const long long*)ei)[e];
        dst = (int)((const long long*)ei)[N_EDGES + e];
    } else {
        src = ((const int*)ei)[e];
        dst = ((const int*)ei)[N_EDGES + e];
    }
    int pos = atomicAdd(&g_cursor[dst], 1);
    g_csr[pos] = src;
}

// ---------------- f32x2 helpers ----------------
__device__ __forceinline__ void fma2(ull& d, ull a, ull b) {
    asm("fma.rn.f32x2 %0, %1, %2, %0;" : "+l"(d) : "l"(a), "l"(b));
}
__device__ __forceinline__ ull dup2(float x) {
    ull r;
    asm("mov.b64 %0, {%1, %1};" : "=l"(r) : "f"(x));
    return r;
}
__device__ __forceinline__ void unpack2(ull v, float& lo, float& hi) {
    asm("mov.b64 {%0, %1}, %2;" : "=f"(lo), "=f"(hi) : "l"(v));
}

// ---------------- dual-output GEMM with f32x2 FMA, tile-range version ----------------
// out[n][h] = X[n][:] . Wcat[h][:] (+ bias on second half), h in [0, HOUT).
// Register-prefetch double buffering on the A tile.
template <int HOUT>
__global__ void __launch_bounds__(256, 1)
k_gemm(const float* __restrict__ X,
       const float* __restrict__ Wa, const float* __restrict__ Wb,
       const float* __restrict__ bias, float* __restrict__ out,
       int tile_begin, int tile_end) {
    constexpr int H2 = HOUT / 2;
    constexpr int J2 = HOUT / 32;
    constexpr int S  = HOUT + 8;
    extern __shared__ float smf[];
    float*  Wt  = smf;                       // [128][S]
    float4* As4 = (float4*)(smf + 128 * S);  // [64][33]
    const int tid = threadIdx.x;
    const float4* X4 = (const float4*)X;

    for (int idx = tid; idx < H2 * 128; idx += 256) {
        int h = idx >> 7, k = idx & 127;
        Wt[k * S + h]      = Wa[idx];
        Wt[k * S + H2 + h] = Wb[idx];
    }

    const int tx = tid & 15, ty = tid >> 4;

    // prefetch first tile into registers
    float4 pre[8];
    {
        int t0 = tile_begin + blockIdx.x;
        if (t0 < tile_end) {
            int n0 = t0 << 6;
#pragma unroll
            for (int u = 0; u < 8; u++) {
                int idx = tid + u * 256;
                int r = idx >> 5, kq = idx & 31;
                int n = n0 + r;
                pre[u] = (n < N_NODES) ? X4[n * 32 + kq]
                                       : make_float4(0.f, 0.f, 0.f, 0.f);
            }
        }
    }
    __syncthreads();   // Wt staged

    for (int tile = tile_begin + blockIdx.x; tile < tile_end; tile += gridDim.x) {
        const int n0 = tile << 6;
#pragma unroll
        for (int u = 0; u < 8; u++) {
            int idx = tid + u * 256;
            As4[(idx >> 5) * 33 + (idx & 31)] = pre[u];
        }
        __syncthreads();

        int nt = tile + gridDim.x;
        if (nt < tile_end) {
            int m0 = nt << 6;
#pragma unroll
            for (int u = 0; u < 8; u++) {
                int idx = tid + u * 256;
                int r = idx >> 5, kq = idx & 31;
                int n = m0 + r;
                pre[u] = (n < N_NODES) ? X4[n * 32 + kq]
                                       : make_float4(0.f, 0.f, 0.f, 0.f);
            }
        }

        ull acc[4][J2];
#pragma unroll
        for (int i = 0; i < 4; i++)
#pragma unroll
            for (int j = 0; j < J2; j++) acc[i][j] = 0ull;

        const float4* Ar = As4 + (ty * 4) * 33;
#pragma unroll 2
        for (int kq = 0; kq < 32; kq++) {
            float4 a0 = Ar[kq];
            float4 a1 = Ar[33 + kq];
            float4 a2 = Ar[66 + kq];
            float4 a3 = Ar[99 + kq];
            ull aa[4][4];
            aa[0][0] = dup2(a0.x); aa[0][1] = dup2(a0.y); aa[0][2] = dup2(a0.z); aa[0][3] = dup2(a0.w);
            aa[1][0] = dup2(a1.x); aa[1][1] = dup2(a1.y); aa[1][2] = dup2(a1.z); aa[1][3] = dup2(a1.w);
            aa[2][0] = dup2(a2.x); aa[2][1] = dup2(a2.y); aa[2][2] = dup2(a2.z); aa[2][3] = dup2(a2.w);
            aa[3][0] = dup2(a3.x); aa[3][1] = dup2(a3.y); aa[3][2] = dup2(a3.z); aa[3][3] = dup2(a3.w);
#pragma unroll
            for (int c = 0; c < 4; c++) {
                const float* wrow = &Wt[(kq * 4 + c) * S];
#pragma unroll
                for (int j = 0; j < J2; j++) {
                    ull w2 = *(const ull*)&wrow[tx * 2 + j * 32];
                    fma2(acc[0][j], aa[0][c], w2);
                    fma2(acc[1][j], aa[1][c], w2);
                    fma2(acc[2][j], aa[2][c], w2);
                    fma2(acc[3][j], aa[3][c], w2);
                }
            }
        }

#pragma unroll
        for (int i = 0; i < 4; i++) {
            int n = n0 + ty * 4 + i;
            if (n < N_NODES) {
#pragma unroll
                for (int j = 0; j < J2; j++) {
                    int h0 = tx * 2 + j * 32;
                    float lo, hi;
                    unpack2(acc[i][j], lo, hi);
                    if (j >= J2 / 2) {                  // root half gets bias
                        lo += __ldg(&bias[h0 - H2]);
                        hi += __ldg(&bias[h0 - H2 + 1]);
                    }
                    *(float2*)&out[n * HOUT + h0] = make_float2(lo, hi);
                }
            }
        }
        __syncthreads();
    }
}

// ---------------- aggregation: t1[n] = relu( sum_{src} v[src] + s[n] ), node range ----------------
__global__ void k_agg1(const float4* __restrict__ vs, float4* __restrict__ t1,
                       int node_begin, int node_end) {
    int gw = node_begin + ((blockIdx.x * blockDim.x + threadIdx.x) >> 5);
    int lane = threadIdx.x & 31;
    if (gw >= node_end) return;
    int beg = g_off[gw], end = g_off[gw + 1];
    float4 acc = vs[gw * 64 + 32 + lane];          // s row
    int j = beg;
    for (; j + 4 <= end; j += 4) {
        int s0 = g_csr[j], s1 = g_csr[j + 1], s2 = g_csr[j + 2], s3 = g_csr[j + 3];
        float4 a = vs[s0 * 64 + lane];
        float4 b = vs[s1 * 64 + lane];
        float4 c = vs[s2 * 64 + lane];
        float4 d = vs[s3 * 64 + lane];
        acc.x += (a.x + b.x) + (c.x + d.x);
        acc.y += (a.y + b.y) + (c.y + d.y);
        acc.z += (a.z + b.z) + (c.z + d.z);
        acc.w += (a.w + b.w) + (c.w + d.w);
    }
    for (; j < end; j++) {
        float4 a = vs[g_csr[j] * 64 + lane];
        acc.x += a.x; acc.y += a.y; acc.z += a.z; acc.w += a.w;
    }
    acc.x = fmaxf(acc.x, 0.f); acc.y = fmaxf(acc.y, 0.f);
    acc.z = fmaxf(acc.z, 0.f); acc.w = fmaxf(acc.w, 0.f);
    t1[gw * 32 + lane] = acc;
}

// ---------------- layer-2 aggregation: out[n] = sum u[src] + r[n]  (64-dim) ----------------
__global__ void k_agg2(const float2* __restrict__ ur, float2* __restrict__ out) {
    int gw = (blockIdx.x * blockDim.x + threadIdx.x) >> 5;
    int lane = threadIdx.x & 31;
    if (gw >= N_NODES) return;
    int beg = g_off[gw], end = g_off[gw + 1];
    float2 acc = ur[gw * 64 + 32 + lane];          // r row
    int j = beg;
    for (; j + 4 <= end; j += 4) {
        int s0 = g_csr[j], s1 = g_csr[j + 1], s2 = g_csr[j + 2], s3 = g_csr[j + 3];
        float2 a = ur[s0 * 64 + lane];
        float2 b = ur[s1 * 64 + lane];
        float2 c = ur[s2 * 64 + lane];
        float2 d = ur[s3 * 64 + lane];
        acc.x += (a.x + b.x) + (c.x + d.x);
        acc.y += (a.y + b.y) + (c.y + d.y);
    }
    for (; j < end; j++) {
        float2 a = ur[g_csr[j] * 64 + lane];
        acc.x += a.x; acc.y += a.y;
    }
    out[gw * 32 + lane] = acc;
}

// ---------------- launch: CSR on side stream; agg1/GEMM2 chunk-pipelined ----------------
extern "C" void kernel_launch(void* const* d_in, const int* in_sizes, int n_in,
                              void* d_out, int out_size) {
    const float* x      = (const float*)d_in[0];
    const void*  ei     = d_in[1];
    const float* Wrel1  = (const float*)d_in[2];
    const float* Wroot1 = (const float*)d_in[3];
    const float* b1     = (const float*)d_in[4];
    const float* Wrel2  = (const float*)d_in[5];
    const float* Wroot2 = (const float*)d_in[6];
    const float* b2     = (const float*)d_in[7];

    void *p_vs1 = nullptr, *p_t1 = nullptr, *p_vs2 = nullptr;
    cudaGetSymbolAddress(&p_vs1, g_vs1);
    cudaGetSymbolAddress(&p_t1, g_t1);
    cudaGetSymbolAddress(&p_vs2, g_vs2);

    const int SM1 = (128 * (256 + 8)) * 4 + 64 * 33 * 16;   // 168,960 B
    const int SM2 = (128 * (128 + 8)) * 4 + 64 * 33 * 16;   // 103,424 B
    cudaFuncSetAttribute(k_gemm<256>, cudaFuncAttributeMaxDynamicSharedMemorySize, SM1);
    cudaFuncSetAttribute(k_gemm<128>, cudaFuncAttributeMaxDynamicSharedMemorySize, SM2);

    static cudaStream_t s1 = nullptr, s2 = nullptr;
    static cudaEvent_t evRoot = nullptr, evCsr = nullptr, evG2 = nullptr;
    static cudaEvent_t evA[NCHUNK] = {};
    if (s1 == nullptr) {
        cudaStreamCreateWithFlags(&s1, cudaStreamNonBlocking);
        cudaStreamCreateWithFlags(&s2, cudaStreamNonBlocking);
        cudaEventCreateWithFlags(&evRoot, cudaEventDisableTiming);
        cudaEventCreateWithFlags(&evCsr, cudaEventDisableTiming);
        cudaEventCreateWithFlags(&evG2, cudaEventDisableTiming);
        for (int c = 0; c < NCHUNK; c++)
            cudaEventCreateWithFlags(&evA[c], cudaEventDisableTiming);
    }

    // fork: CSR build on s1, concurrent with layer-1 GEMM on stream 0
    cudaEventRecord(evRoot, 0);
    cudaStreamWaitEvent(s1, evRoot, 0);
    cudaStreamWaitEvent(s2, evRoot, 0);
    k_zero_detect<<<(N_NODES + 255) / 256, 256, 0, s1>>>((const int*)ei);
    k_hist<<<(N_EDGES + 255) / 256, 256, 0, s1>>>(ei);
    k_scan1<<<NBLK, SCAN_BLK, 0, s1>>>();
    k_scan2<<<1, SCAN_BLK, 0, s1>>>();
    k_scan3<<<NBLK, SCAN_BLK, 0, s1>>>();
    k_scatter<<<(N_EDGES + 255) / 256, 256, 0, s1>>>(ei);
    cudaEventRecord(evCsr, s1);

    // layer-1 GEMM x -> [v|s] (independent of CSR)
    k_gemm<256><<<148, 256, SM1>>>(x, Wrel1, Wroot1, b1, (float*)p_vs1, 0, NTILES);

    // join CSR before first agg
    cudaStreamWaitEvent(0, evCsr, 0);

    // pipelined: agg1 chunk c on stream 0  ->  GEMM2 chunk c on s2
    const int tile_per = (NTILES + NCHUNK - 1) / NCHUNK;     // 196
    for (int c = 0; c < NCHUNK; c++) {
        int t0 = c * tile_per;
        int t1e = min(t0 + tile_per, NTILES);
        if (t0 >= t1e) break;
        int nb = t0 * 64;
        int ne = min(t1e * 64, N_NODES);
        int warps = ne - nb;
        k_agg1<<<(warps * 32 + 255) / 256, 256>>>((const float4*)p_vs1,
                                                  (float4*)p_t1, nb, ne);
        cudaEventRecord(evA[c], 0);
        cudaStreamWaitEvent(s2, evA[c], 0);
        k_gemm<128><<<148, 256, SM2, s2>>>((const float*)p_t1, Wrel2, Wroot2, b2,
                                           (float*)p_vs2, t0, t1e);
    }
    cudaEventRecord(evG2, s2);
    cudaStreamWaitEvent(0, evG2, 0);

    // final aggregation (needs all of vs2)
    k_agg2<<<(N_NODES * 32 + 255) / 256, 256>>>((const float2*)p_vs2, (float2*)d_out);
}

// round 7
// speedup vs baseline: 1.2630x; 1.0983x over previous
#include <cuda_runtime.h>
#include <cuda_bf16.h>
#include <cstdint>

#define N_NODES 50000
#define N_EDGES 800000

#define SCAN_BLK 256
#define NBLK ((N_NODES + SCAN_BLK - 1) / SCAN_BLK)   // 196
#define NT128 ((N_NODES + 127) / 128)                // 391

typedef unsigned long long ull;

// ---------------- device scratch (static, no allocation) ----------------
__device__ float g_vs1[N_NODES * 256];   // layer1 out: [v(128) | s(128)] per node
__device__ float g_t1 [N_NODES * 128];   // layer1 activations
__device__ float g_vs2[N_NODES * 128];   // layer2 out: [u(64) | r(64)] per node
__device__ int   g_deg[N_NODES];
__device__ int   g_off[N_NODES + 1];
__device__ int   g_cursor[N_NODES];
__device__ int   g_csr[N_EDGES];
__device__ int   g_bsum[NBLK];
__device__ int   g_is64;

// ================= CSR build =================
__global__ void k_zero_detect(const int* __restrict__ ei32) {
    int i = blockIdx.x * blockDim.x + threadIdx.x;
    if (i < N_NODES) g_deg[i] = 0;
    if (i == 0) {
        int orv = 0;
#pragma unroll
        for (int k = 0; k < 64; k++) orv |= ei32[2 * k + 1];
        g_is64 = (orv == 0) ? 1 : 0;
    }
}

__global__ void k_hist(const void* __restrict__ ei) {
    int e = blockIdx.x * blockDim.x + threadIdx.x;
    if (e >= N_EDGES) return;
    int dst = g_is64 ? (int)((const long long*)ei)[N_EDGES + e]
                     : ((const int*)ei)[N_EDGES + e];
    atomicAdd(&g_deg[dst], 1);
}

__global__ void k_scan1() {
    __shared__ int sh[SCAN_BLK];
    int i = blockIdx.x * SCAN_BLK + threadIdx.x;
    int v = (i < N_NODES) ? g_deg[i] : 0;
    sh[threadIdx.x] = v;
    __syncthreads();
    for (int off = SCAN_BLK / 2; off > 0; off >>= 1) {
        if (threadIdx.x < off) sh[threadIdx.x] += sh[threadIdx.x + off];
        __syncthreads();
    }
    if (threadIdx.x == 0) g_bsum[blockIdx.x] = sh[0];
}

__global__ void k_scan2() {
    __shared__ int sh[SCAN_BLK];
    int t = threadIdx.x;
    int v = (t < NBLK) ? g_bsum[t] : 0;
    sh[t] = v;
    __syncthreads();
    for (int off = 1; off < SCAN_BLK; off <<= 1) {
        int add = (t >= off) ? sh[t - off] : 0;
        __syncthreads();
        sh[t] += add;
        __syncthreads();
    }
    if (t < NBLK) g_bsum[t] = sh[t] - v;
    if (t == 0) g_off[N_NODES] = N_EDGES;
}

__global__ void k_scan3() {
    __shared__ int sh[SCAN_BLK];
    int t = threadIdx.x;
    int i = blockIdx.x * SCAN_BLK + t;
    int v = (i < N_NODES) ? g_deg[i] : 0;
    sh[t] = v;
    __syncthreads();
    for (int off = 1; off < SCAN_BLK; off <<= 1) {
        int add = (t >= off) ? sh[t - off] : 0;
        __syncthreads();
        sh[t] += add;
        __syncthreads();
    }
    if (i < N_NODES) {
        int o = g_bsum[blockIdx.x] + sh[t] - v;
        g_off[i] = o;
        g_cursor[i] = o;
    }
}

__global__ void k_scatter(const void* __restrict__ ei) {
    int e = blockIdx.x * blockDim.x + threadIdx.x;
    if (e >= N_EDGES) return;
    int src, dst;
    if (g_is64) {
        src = (int)((const long long*)ei)[e];
        dst = (int)((const long long*)ei)[N_EDGES + e];
    } else {
        src = ((const int*)ei)[e];
        dst = ((const int*)ei)[N_EDGES + e];
    }
    int pos = atomicAdd(&g_cursor[dst], 1);
    g_csr[pos] = src;
}

// ================= bf16 split helpers =================
__device__ __forceinline__ void decomp2(float x, float y, uint32_t& hp, uint32_t& lp) {
    __nv_bfloat16 hx = __float2bfloat16(x);
    __nv_bfloat16 hy = __float2bfloat16(y);
    float rx = x - __bfloat162float(hx);
    float ry = y - __bfloat162float(hy);
    __nv_bfloat16 lx = __float2bfloat16(rx);
    __nv_bfloat16 ly = __float2bfloat16(ry);
    hp = (uint32_t)__bfloat16_as_ushort(hx) | ((uint32_t)__bfloat16_as_ushort(hy) << 16);
    lp = (uint32_t)__bfloat16_as_ushort(lx) | ((uint32_t)__bfloat16_as_ushort(ly) << 16);
}

__device__ __forceinline__ void mma16816(float* c, const uint32_t* a, uint2 b) {
    asm volatile(
        "mma.sync.aligned.m16n8k16.row.col.f32.bf16.bf16.f32 "
        "{%0,%1,%2,%3}, {%4,%5,%6,%7}, {%8,%9}, {%0,%1,%2,%3};"
        : "+f"(c[0]), "+f"(c[1]), "+f"(c[2]), "+f"(c[3])
        : "r"(a[0]), "r"(a[1]), "r"(a[2]), "r"(a[3]), "r"(b.x), "r"(b.y));
}

// ================= tensor-core dual GEMM via mma.sync =================
// out[n][0:NCOLS] = [ X.Wa^T | X.Wb^T + bias ], K=128.
// 3-pass bf16 split: Ahi.Bhi + Ahi.Blo + Alo.Bhi (fp32 accum in registers).
// smem holds PRE-SWIZZLED mma fragments:
//   A[half][ks(8)][mt(8)][lane(32)][4] u32   (32KB per half)
//   B[half][ks(8)][nt(NT)][lane(32)][2] u32  (NT*2KB per half)
template <int NCOLS>
__global__ void __launch_bounds__(256, 1)
k_mma(const float* __restrict__ X,
      const float* __restrict__ Wa, const float* __restrict__ Wb,
      const float* __restrict__ bias, float* __restrict__ out) {
    constexpr int NT   = NCOLS / 8;                 // 32 or 16
    constexpr int HB   = NCOLS / 2;
    constexpr int MT_W = (NCOLS == 256) ? 2 : 1;    // m-tiles per warp
    constexpr int NT_W = 16;                        // n-tiles per warp
    extern __shared__ uint32_t sm[];
    uint32_t* Ah = sm;
    uint32_t* Al = sm + 8192;
    uint32_t* Bh = sm + 16384;
    uint32_t* Bl = Bh + NT * 512;

    const int tid = threadIdx.x;
    const int w = tid >> 5, lane = tid & 31;
    const int wm = (NCOLS == 256) ? (w >> 1) : w;   // warp m position
    const int wn = (NCOLS == 256) ? (w & 1) : 0;    // warp n half

    // ---- stage B fragments hi/lo (once per block) ----
    for (int idx = tid; idx < NCOLS * 64; idx += 256) {
        int h  = idx >> 6;
        int c2 = (idx & 63) << 1;
        const float* src = (h < HB) ? (Wa + h * 128 + c2) : (Wb + (h - HB) * 128 + c2);
        float2 wv = *(const float2*)src;
        uint32_t hp, lp;
        decomp2(wv.x, wv.y, hp, lp);
        int nt = h >> 3;
        int ln = ((h & 7) << 2) | ((c2 >> 1) & 3);
        int ks = c2 >> 4;
        int rg = (c2 >> 3) & 1;
        int addr = ((ks * NT + nt) * 32 + ln) * 2 + rg;
        Bh[addr] = hp;
        Bl[addr] = lp;
    }
    __syncthreads();

    for (int tile = blockIdx.x; tile < NT128; tile += gridDim.x) {
        const int n0 = tile << 7;

        // ---- stage A tile fragments hi/lo ----
        for (int idx = tid; idx < 128 * 64; idx += 256) {
            int r  = idx >> 6;
            int c2 = (idx & 63) << 1;
            int n = n0 + r;
            float2 v = (n < N_NODES) ? *(const float2*)(X + (size_t)n * 128 + c2)
                                     : make_float2(0.f, 0.f);
            uint32_t hp, lp;
            decomp2(v.x, v.y, hp, lp);
            int mt = r >> 4, rr = r & 15;
            int ln = ((rr & 7) << 2) | ((c2 >> 1) & 3);
            int ks = c2 >> 4;
            int rg = ((rr >> 3) & 1) | (((c2 >> 3) & 1) << 1);
            int addr = (((ks << 3) | mt) * 32 + ln) * 4 + rg;
            Ah[addr] = hp;
            Al[addr] = lp;
        }
        __syncthreads();

        float acc[MT_W][NT_W][4];
#pragma unroll
        for (int m = 0; m < MT_W; m++)
#pragma unroll
            for (int t = 0; t < NT_W; t++)
#pragma unroll
                for (int c = 0; c < 4; c++) acc[m][t][c] = 0.f;

        const uint32_t* Ap[3] = { Ah, Ah, Al };
        const uint32_t* Bp[3] = { Bh, Bl, Bh };
#pragma unroll
        for (int p = 0; p < 3; p++) {
            const uint32_t* A = Ap[p];
            const uint32_t* B = Bp[p];
#pragma unroll
            for (int ks = 0; ks < 8; ks++) {
                uint32_t af[MT_W][4];
#pragma unroll
                for (int m = 0; m < MT_W; m++) {
                    int mt = wm * MT_W + m;
                    uint4 v = *(const uint4*)&A[(((ks << 3) | mt) * 32 + lane) * 4];
                    af[m][0] = v.x; af[m][1] = v.y; af[m][2] = v.z; af[m][3] = v.w;
                }
#pragma unroll
                for (int t = 0; t < NT_W; t++) {
                    int nt = wn * NT_W + t;
                    uint2 bv = *(const uint2*)&B[((ks * NT + nt) * 32 + lane) * 2];
#pragma unroll
                    for (int m = 0; m < MT_W; m++)
                        mma16816(acc[m][t], af[m], bv);
                }
            }
        }
        __syncthreads();   // all warps done reading A before next tile restages

        // ---- epilogue ----
#pragma unroll
        for (int m = 0; m < MT_W; m++) {
            int row0 = n0 + (wm * MT_W + m) * 16 + (lane >> 2);
#pragma unroll
            for (int t = 0; t < NT_W; t++) {
                int col = (wn * NT_W + t) * 8 + ((lane & 3) << 1);
                float bx = 0.f, by = 0.f;
                if (col >= HB) {
                    bx = __ldg(&bias[col - HB]);
                    by = __ldg(&bias[col - HB + 1]);
                }
                if (row0 < N_NODES)
                    *(float2*)&out[(size_t)row0 * NCOLS + col] =
                        make_float2(acc[m][t][0] + bx, acc[m][t][1] + by);
                if (row0 + 8 < N_NODES)
                    *(float2*)&out[(size_t)(row0 + 8) * NCOLS + col] =
                        make_float2(acc[m][t][2] + bx, acc[m][t][3] + by);
            }
        }
    }
}

// ================= aggregations =================
__global__ void k_agg1(const float4* __restrict__ vs, float4* __restrict__ t1) {
    int gw = (blockIdx.x * blockDim.x + threadIdx.x) >> 5;
    int lane = threadIdx.x & 31;
    if (gw >= N_NODES) return;
    int beg = g_off[gw], end = g_off[gw + 1];
    float4 acc = vs[gw * 64 + 32 + lane];          // s row
    int j = beg;
    for (; j + 4 <= end; j += 4) {
        int s0 = g_csr[j], s1 = g_csr[j + 1], s2 = g_csr[j + 2], s3 = g_csr[j + 3];
        float4 a = vs[s0 * 64 + lane];
        float4 b = vs[s1 * 64 + lane];
        float4 c = vs[s2 * 64 + lane];
        float4 d = vs[s3 * 64 + lane];
        acc.x += (a.x + b.x) + (c.x + d.x);
        acc.y += (a.y + b.y) + (c.y + d.y);
        acc.z += (a.z + b.z) + (c.z + d.z);
        acc.w += (a.w + b.w) + (c.w + d.w);
    }
    for (; j < end; j++) {
        float4 a = vs[g_csr[j] * 64 + lane];
        acc.x += a.x; acc.y += a.y; acc.z += a.z; acc.w += a.w;
    }
    acc.x = fmaxf(acc.x, 0.f); acc.y = fmaxf(acc.y, 0.f);
    acc.z = fmaxf(acc.z, 0.f); acc.w = fmaxf(acc.w, 0.f);
    t1[gw * 32 + lane] = acc;
}

__global__ void k_agg2(const float2* __restrict__ ur, float2* __restrict__ out) {
    int gw = (blockIdx.x * blockDim.x + threadIdx.x) >> 5;
    int lane = threadIdx.x & 31;
    if (gw >= N_NODES) return;
    int beg = g_off[gw], end = g_off[gw + 1];
    float2 acc = ur[gw * 64 + 32 + lane];          // r row
    int j = beg;
    for (; j + 4 <= end; j += 4) {
        int s0 = g_csr[j], s1 = g_csr[j + 1], s2 = g_csr[j + 2], s3 = g_csr[j + 3];
        float2 a = ur[s0 * 64 + lane];
        float2 b = ur[s1 * 64 + lane];
        float2 c = ur[s2 * 64 + lane];
        float2 d = ur[s3 * 64 + lane];
        acc.x += (a.x + b.x) + (c.x + d.x);
        acc.y += (a.y + b.y) + (c.y + d.y);
    }
    for (; j < end; j++) {
        float2 a = ur[g_csr[j] * 64 + lane];
        acc.x += a.x; acc.y += a.y;
    }
    out[gw * 32 + lane] = acc;
}

// ================= launch =================
extern "C" void kernel_launch(void* const* d_in, const int* in_sizes, int n_in,
                              void* d_out, int out_size) {
    const float* x      = (const float*)d_in[0];
    const void*  ei     = d_in[1];
    const float* Wrel1  = (const float*)d_in[2];
    const float* Wroot1 = (const float*)d_in[3];
    const float* b1     = (const float*)d_in[4];
    const float* Wrel2  = (const float*)d_in[5];
    const float* Wroot2 = (const float*)d_in[6];
    const float* b2     = (const float*)d_in[7];

    void *p_vs1 = nullptr, *p_t1 = nullptr, *p_vs2 = nullptr;
    cudaGetSymbolAddress(&p_vs1, g_vs1);
    cudaGetSymbolAddress(&p_t1, g_t1);
    cudaGetSymbolAddress(&p_vs2, g_vs2);

    const int SM1 = (16384 + 2 * 32 * 512) * 4;   // 196,608 B (A hi/lo + B hi/lo, NT=32)
    const int SM2 = (16384 + 2 * 16 * 512) * 4;   // 131,072 B (NT=16)
    cudaFuncSetAttribute(k_mma<256>, cudaFuncAttributeMaxDynamicSharedMemorySize, SM1);
    cudaFuncSetAttribute(k_mma<128>, cudaFuncAttributeMaxDynamicSharedMemorySize, SM2);

    static cudaStream_t s1 = nullptr;
    static cudaEvent_t evRoot = nullptr, evCsr = nullptr;
    if (s1 == nullptr) {
        cudaStreamCreateWithFlags(&s1, cudaStreamNonBlocking);
        cudaEventCreateWithFlags(&evRoot, cudaEventDisableTiming);
        cudaEventCreateWithFlags(&evCsr, cudaEventDisableTiming);
    }

    // fork: CSR build on s1, concurrent with layer-1 GEMM on stream 0
    cudaEventRecord(evRoot, 0);
    cudaStreamWaitEvent(s1, evRoot, 0);
    k_zero_detect<<<(N_NODES + 255) / 256, 256, 0, s1>>>((const int*)ei);
    k_hist<<<(N_EDGES + 255) / 256, 256, 0, s1>>>(ei);
    k_scan1<<<NBLK, SCAN_BLK, 0, s1>>>();
    k_scan2<<<1, SCAN_BLK, 0, s1>>>();
    k_scan3<<<NBLK, SCAN_BLK, 0, s1>>>();
    k_scatter<<<(N_EDGES + 255) / 256, 256, 0, s1>>>(ei);
    cudaEventRecord(evCsr, s1);

    // layer-1 GEMM (mma.sync bf16 split): x -> [v | s]
    k_mma<256><<<148, 256, SM1>>>(x, Wrel1, Wroot1, b1, (float*)p_vs1);

    // join CSR, then aggregate + relu
    cudaStreamWaitEvent(0, evCsr, 0);
    k_agg1<<<(N_NODES * 32 + 255) / 256, 256>>>((const float4*)p_vs1, (float4*)p_t1);

    // layer-2 GEMM: t1 -> [u | r]
    k_mma<128><<<148, 256, SM2>>>((const float*)p_t1, Wrel2, Wroot2, b2, (float*)p_vs2);

    // final aggregation
    k_agg2<<<(N_NODES * 32 + 255) / 256, 256>>>((const float2*)p_vs2, (float2*)d_out);
}